// round 1
// baseline (speedup 1.0000x reference)
#include <cuda_runtime.h>
#include <cuda_bf16.h>
#include <cstdint>

// Problem dims (fixed by the reference)
#define NROWS   16384
#define INDIM   256
#define OUTDIM  128

// Tiling
#define BM 128
#define BN 128
#define BK 32
#define A_STRIDE 36    // padded row stride (floats) for [row][k] tiles -> conflict-free frag loads
#define B_STRIDE 136   // padded row stride (floats) for [k][n] tiles  -> conflict-free frag loads

// Intermediate h = x @ W^T + b, stored [NROWS][OUTDIM] row-major
__device__ float g_h[(size_t)NROWS * OUTDIM];

__device__ __forceinline__ uint32_t f2tf32(float f) {
    uint32_t u;
    asm("cvt.rna.tf32.f32 %0, %1;" : "=r"(u) : "f"(f));
    return u;
}

__device__ __forceinline__ void mma_tf32(float c[4], const uint32_t a[4], const uint32_t b[2]) {
    asm volatile(
        "mma.sync.aligned.m16n8k8.row.col.f32.tf32.tf32.f32 "
        "{%0,%1,%2,%3}, {%4,%5,%6,%7}, {%8,%9}, {%0,%1,%2,%3};"
        : "+f"(c[0]), "+f"(c[1]), "+f"(c[2]), "+f"(c[3])
        : "r"(a[0]), "r"(a[1]), "r"(a[2]), "r"(a[3]), "r"(b[0]), "r"(b[1]));
}

__device__ __forceinline__ void cp_async16(uint32_t smem_addr, const float* gmem) {
    asm volatile("cp.async.cg.shared.global [%0], [%1], 16;" :: "r"(smem_addr), "l"(gmem));
}
__device__ __forceinline__ void cp_commit() { asm volatile("cp.async.commit_group;"); }
__device__ __forceinline__ void cp_wait0()  { asm volatile("cp.async.wait_group 0;" ::: "memory"); }

// Load a [128 rows x 32 k] tile (row-major source, leading dim ldK) into smem [row][k] stride A_STRIDE.
// 1024 x 16B chunks, 4 per thread (256 threads).
__device__ __forceinline__ void load_tile_rowmajor(uint32_t sbase, const float* src,
                                                   int row0, int k0, int ldK, int tid) {
#pragma unroll
    for (int t = 0; t < 4; t++) {
        int idx = tid + t * 256;
        int r  = idx >> 3;            // 0..127
        int cc = (idx & 7) << 2;      // 0,4,...,28
        cp_async16(sbase + (uint32_t)(r * A_STRIDE + cc) * 4u,
                   src + (size_t)(row0 + r) * ldK + k0 + cc);
    }
}

// Load a [32 k x 128 n] tile from row-major [K x 128] source into smem [k][n] stride B_STRIDE.
__device__ __forceinline__ void load_tile_kn(uint32_t sbase, const float* src,
                                             int k0, int tid) {
#pragma unroll
    for (int t = 0; t < 4; t++) {
        int idx = tid + t * 256;
        int k = idx >> 5;             // 0..31
        int n = (idx & 31) << 2;      // 0,4,...,124
        cp_async16(sbase + (uint32_t)(k * B_STRIDE + n) * 4u,
                   src + (size_t)(k0 + k) * OUTDIM + n);
    }
}

// ============================================================================
// Stage 1: h[n][o] = sum_i x[n][i] * W[o][i] + b[o]
// A = x [NROWS, INDIM] row-major; B = W [OUTDIM, INDIM] row-major (N x K form).
// Both tiles use the [row][k] stride-36 smem layout.
// ============================================================================
__global__ __launch_bounds__(256, 1)
void gemm_lin(const float* __restrict__ x, const float* __restrict__ W,
              const float* __restrict__ bias) {
    extern __shared__ float smem[];
    float* As0 = smem;
    float* As1 = As0 + BM * A_STRIDE;
    float* Ws0 = As1 + BM * A_STRIDE;
    float* Ws1 = Ws0 + BN * A_STRIDE;

    const int tid  = threadIdx.x;
    const int lane = tid & 31, wid = tid >> 5;
    const int warpM = wid >> 2, warpN = wid & 3;
    const int bm = blockIdx.x;

    uint32_t sA0 = (uint32_t)__cvta_generic_to_shared(As0);
    uint32_t sA1 = (uint32_t)__cvta_generic_to_shared(As1);
    uint32_t sW0 = (uint32_t)__cvta_generic_to_shared(Ws0);
    uint32_t sW1 = (uint32_t)__cvta_generic_to_shared(Ws1);

    float c[4][4][4];
#pragma unroll
    for (int i = 0; i < 4; i++)
#pragma unroll
        for (int j = 0; j < 4; j++)
#pragma unroll
            for (int k = 0; k < 4; k++) c[i][j][k] = 0.0f;

    load_tile_rowmajor(sA0, x, bm * BM, 0, INDIM, tid);
    load_tile_rowmajor(sW0, W, 0, 0, INDIM, tid);
    cp_commit();

    const int KT = INDIM / BK; // 8
    for (int kt = 0; kt < KT; kt++) {
        cp_wait0();
        __syncthreads();
        if (kt + 1 < KT) {
            uint32_t dA = ((kt + 1) & 1) ? sA1 : sA0;
            uint32_t dW = ((kt + 1) & 1) ? sW1 : sW0;
            load_tile_rowmajor(dA, x, bm * BM, (kt + 1) * BK, INDIM, tid);
            load_tile_rowmajor(dW, W, 0, (kt + 1) * BK, INDIM, tid);
            cp_commit();
        }
        const float* As = (kt & 1) ? As1 : As0;
        const float* Ws = (kt & 1) ? Ws1 : Ws0;

#pragma unroll
        for (int kk = 0; kk < BK; kk += 8) {
            uint32_t af[4][4];
#pragma unroll
            for (int mi = 0; mi < 4; mi++) {
                int r  = warpM * 64 + mi * 16 + (lane >> 2);
                int cc = kk + (lane & 3);
                af[mi][0] = f2tf32(As[r * A_STRIDE + cc]);
                af[mi][1] = f2tf32(As[(r + 8) * A_STRIDE + cc]);
                af[mi][2] = f2tf32(As[r * A_STRIDE + cc + 4]);
                af[mi][3] = f2tf32(As[(r + 8) * A_STRIDE + cc + 4]);
            }
            uint32_t bf[4][2];
#pragma unroll
            for (int ni = 0; ni < 4; ni++) {
                int n = warpN * 32 + ni * 8 + (lane >> 2);
                int k = kk + (lane & 3);
                bf[ni][0] = f2tf32(Ws[n * A_STRIDE + k]);
                bf[ni][1] = f2tf32(Ws[n * A_STRIDE + k + 4]);
            }
#pragma unroll
            for (int mi = 0; mi < 4; mi++)
#pragma unroll
                for (int ni = 0; ni < 4; ni++) mma_tf32(c[mi][ni], af[mi], bf[ni]);
        }
    }

    // Epilogue: add bias, write h
#pragma unroll
    for (int ni = 0; ni < 4; ni++) {
        int cn = warpN * 32 + ni * 8 + ((lane & 3) << 1);
        float2 bb = *(const float2*)(bias + cn);
#pragma unroll
        for (int mi = 0; mi < 4; mi++) {
            int r = bm * BM + warpM * 64 + mi * 16 + (lane >> 2);
            float2 v0 = make_float2(c[mi][ni][0] + bb.x, c[mi][ni][1] + bb.y);
            float2 v1 = make_float2(c[mi][ni][2] + bb.x, c[mi][ni][3] + bb.y);
            *(float2*)&g_h[(size_t)r * OUTDIM + cn]       = v0;
            *(float2*)&g_h[(size_t)(r + 8) * OUTDIM + cn] = v1;
        }
    }
}

// ============================================================================
// Stage 2: out = A_hat @ h.  A_hat [NROWS, NROWS] row-major, h [NROWS, OUTDIM].
// ============================================================================
__global__ __launch_bounds__(256, 1)
void gemm_aggr(const float* __restrict__ A, float* __restrict__ out) {
    extern __shared__ float smem[];
    float* As0 = smem;
    float* As1 = As0 + BM * A_STRIDE;
    float* Bs0 = As1 + BM * A_STRIDE;
    float* Bs1 = Bs0 + BK * B_STRIDE;

    const int tid  = threadIdx.x;
    const int lane = tid & 31, wid = tid >> 5;
    const int warpM = wid >> 2, warpN = wid & 3;
    const int bm = blockIdx.x;

    uint32_t sA0 = (uint32_t)__cvta_generic_to_shared(As0);
    uint32_t sA1 = (uint32_t)__cvta_generic_to_shared(As1);
    uint32_t sB0 = (uint32_t)__cvta_generic_to_shared(Bs0);
    uint32_t sB1 = (uint32_t)__cvta_generic_to_shared(Bs1);

    float c[4][4][4];
#pragma unroll
    for (int i = 0; i < 4; i++)
#pragma unroll
        for (int j = 0; j < 4; j++)
#pragma unroll
            for (int k = 0; k < 4; k++) c[i][j][k] = 0.0f;

    load_tile_rowmajor(sA0, A, bm * BM, 0, NROWS, tid);
    load_tile_kn(sB0, g_h, 0, tid);
    cp_commit();

    const int KT = NROWS / BK; // 512
    for (int kt = 0; kt < KT; kt++) {
        cp_wait0();
        __syncthreads();
        if (kt + 1 < KT) {
            uint32_t dA = ((kt + 1) & 1) ? sA1 : sA0;
            uint32_t dB = ((kt + 1) & 1) ? sB1 : sB0;
            load_tile_rowmajor(dA, A, bm * BM, (kt + 1) * BK, NROWS, tid);
            load_tile_kn(dB, g_h, (kt + 1) * BK, tid);
            cp_commit();
        }
        const float* As = (kt & 1) ? As1 : As0;
        const float* Bs = (kt & 1) ? Bs1 : Bs0;

#pragma unroll
        for (int kk = 0; kk < BK; kk += 8) {
            uint32_t af[4][4];
#pragma unroll
            for (int mi = 0; mi < 4; mi++) {
                int r  = warpM * 64 + mi * 16 + (lane >> 2);
                int cc = kk + (lane & 3);
                af[mi][0] = f2tf32(As[r * A_STRIDE + cc]);
                af[mi][1] = f2tf32(As[(r + 8) * A_STRIDE + cc]);
                af[mi][2] = f2tf32(As[r * A_STRIDE + cc + 4]);
                af[mi][3] = f2tf32(As[(r + 8) * A_STRIDE + cc + 4]);
            }
            uint32_t bf[4][2];
#pragma unroll
            for (int ni = 0; ni < 4; ni++) {
                int n = warpN * 32 + ni * 8 + (lane >> 2);
                int k = kk + (lane & 3);
                bf[ni][0] = f2tf32(Bs[k * B_STRIDE + n]);
                bf[ni][1] = f2tf32(Bs[(k + 4) * B_STRIDE + n]);
            }
#pragma unroll
            for (int mi = 0; mi < 4; mi++)
#pragma unroll
                for (int ni = 0; ni < 4; ni++) mma_tf32(c[mi][ni], af[mi], bf[ni]);
        }
    }

    // Epilogue
#pragma unroll
    for (int mi = 0; mi < 4; mi++)
#pragma unroll
        for (int ni = 0; ni < 4; ni++) {
            int r  = bm * BM + warpM * 64 + mi * 16 + (lane >> 2);
            int cn = warpN * 32 + ni * 8 + ((lane & 3) << 1);
            *(float2*)&out[(size_t)r * OUTDIM + cn] =
                make_float2(c[mi][ni][0], c[mi][ni][1]);
            *(float2*)&out[(size_t)(r + 8) * OUTDIM + cn] =
                make_float2(c[mi][ni][2], c[mi][ni][3]);
        }
}

// Shared memory sizes (bytes)
static const int SMEM_LIN  = (2 * BM * A_STRIDE + 2 * BN * A_STRIDE) * 4;  // 73728
static const int SMEM_AGGR = (2 * BM * A_STRIDE + 2 * BK * B_STRIDE) * 4;  // 71680

extern "C" void kernel_launch(void* const* d_in, const int* in_sizes, int n_in,
                              void* d_out, int out_size) {
    const float* x     = (const float*)d_in[0];
    const float* A_hat = (const float*)d_in[1];
    const float* W     = (const float*)d_in[2];
    const float* b     = (const float*)d_in[3];
    float* out = (float*)d_out;

    cudaFuncSetAttribute(gemm_lin,  cudaFuncAttributeMaxDynamicSharedMemorySize, SMEM_LIN);
    cudaFuncSetAttribute(gemm_aggr, cudaFuncAttributeMaxDynamicSharedMemorySize, SMEM_AGGR);

    gemm_lin<<<NROWS / BM, 256, SMEM_LIN>>>(x, W, b);
    gemm_aggr<<<NROWS / BM, 256, SMEM_AGGR>>>(A_hat, out);
}

// round 2
// speedup vs baseline: 1.2215x; 1.2215x over previous
#include <cuda_runtime.h>
#include <cuda_bf16.h>
#include <cstdint>

// Problem dims (fixed by the reference)
#define NROWS   16384
#define INDIM   256
#define OUTDIM  128

// Tiling
#define BM 128
#define BN 128
#define BK 32
#define A_STRIDE 36    // padded row stride (floats) for [row][k] tiles -> conflict-free frag loads
#define B_STRIDE 136   // padded row stride (floats) for [k][n] tiles  -> conflict-free frag loads
#define S_STAGES 5     // pipeline depth for the aggregation GEMM

#define A_STAGE_FLOATS (BM * A_STRIDE)   // 4608
#define B_STAGE_FLOATS (BK * B_STRIDE)   // 4352

// Intermediate h = x @ W^T + b, stored [NROWS][OUTDIM] row-major
__device__ float g_h[(size_t)NROWS * OUTDIM];

// tf32 fast path: raw fp32 bits fed to the tf32 MMA (HW truncates low mantissa).
__device__ __forceinline__ uint32_t f2u(float f) { return __float_as_uint(f); }

__device__ __forceinline__ void mma_tf32(float c[4], const uint32_t a[4], const uint32_t b[2]) {
    asm volatile(
        "mma.sync.aligned.m16n8k8.row.col.f32.tf32.tf32.f32 "
        "{%0,%1,%2,%3}, {%4,%5,%6,%7}, {%8,%9}, {%0,%1,%2,%3};"
        : "+f"(c[0]), "+f"(c[1]), "+f"(c[2]), "+f"(c[3])
        : "r"(a[0]), "r"(a[1]), "r"(a[2]), "r"(a[3]), "r"(b[0]), "r"(b[1]));
}

__device__ __forceinline__ void cp_async16(uint32_t smem_addr, const float* gmem) {
    asm volatile("cp.async.cg.shared.global [%0], [%1], 16;" :: "r"(smem_addr), "l"(gmem));
}
__device__ __forceinline__ void cp_commit() { asm volatile("cp.async.commit_group;"); }

// Load a [128 rows x 32 k] tile (row-major source, leading dim ldK) into smem [row][k] stride A_STRIDE.
__device__ __forceinline__ void load_tile_rowmajor(uint32_t sbase, const float* src,
                                                   int row0, int k0, int ldK, int tid) {
#pragma unroll
    for (int t = 0; t < 4; t++) {
        int idx = tid + t * 256;
        int r  = idx >> 3;            // 0..127
        int cc = (idx & 7) << 2;      // 0,4,...,28
        cp_async16(sbase + (uint32_t)(r * A_STRIDE + cc) * 4u,
                   src + (size_t)(row0 + r) * ldK + k0 + cc);
    }
}

// Load a [32 k x 128 n] tile from row-major [K x 128] source into smem [k][n] stride B_STRIDE.
__device__ __forceinline__ void load_tile_kn(uint32_t sbase, const float* src,
                                             int k0, int tid) {
#pragma unroll
    for (int t = 0; t < 4; t++) {
        int idx = tid + t * 256;
        int k = idx >> 5;             // 0..31
        int n = (idx & 31) << 2;      // 0,4,...,124
        cp_async16(sbase + (uint32_t)(k * B_STRIDE + n) * 4u,
                   src + (size_t)(k0 + k) * OUTDIM + n);
    }
}

// ============================================================================
// Stage 1: h[n][o] = sum_i x[n][i] * W[o][i] + b[o]   (small: ~1 GFLOP)
// ============================================================================
__global__ __launch_bounds__(256, 1)
void gemm_lin(const float* __restrict__ x, const float* __restrict__ W,
              const float* __restrict__ bias) {
    extern __shared__ float smem[];
    float* As0 = smem;
    float* As1 = As0 + BM * A_STRIDE;
    float* Ws0 = As1 + BM * A_STRIDE;
    float* Ws1 = Ws0 + BN * A_STRIDE;

    const int tid  = threadIdx.x;
    const int lane = tid & 31, wid = tid >> 5;
    const int warpM = wid >> 2, warpN = wid & 3;
    const int bm = blockIdx.x;

    uint32_t sA0 = (uint32_t)__cvta_generic_to_shared(As0);
    uint32_t sA1 = (uint32_t)__cvta_generic_to_shared(As1);
    uint32_t sW0 = (uint32_t)__cvta_generic_to_shared(Ws0);
    uint32_t sW1 = (uint32_t)__cvta_generic_to_shared(Ws1);

    float c[4][4][4];
#pragma unroll
    for (int i = 0; i < 4; i++)
#pragma unroll
        for (int j = 0; j < 4; j++)
#pragma unroll
            for (int k = 0; k < 4; k++) c[i][j][k] = 0.0f;

    load_tile_rowmajor(sA0, x, bm * BM, 0, INDIM, tid);
    load_tile_rowmajor(sW0, W, 0, 0, INDIM, tid);
    cp_commit();

    const int KT = INDIM / BK; // 8
    for (int kt = 0; kt < KT; kt++) {
        asm volatile("cp.async.wait_group 0;" ::: "memory");
        __syncthreads();
        if (kt + 1 < KT) {
            uint32_t dA = ((kt + 1) & 1) ? sA1 : sA0;
            uint32_t dW = ((kt + 1) & 1) ? sW1 : sW0;
            load_tile_rowmajor(dA, x, bm * BM, (kt + 1) * BK, INDIM, tid);
            load_tile_rowmajor(dW, W, 0, (kt + 1) * BK, INDIM, tid);
            cp_commit();
        }
        const float* As = (kt & 1) ? As1 : As0;
        const float* Ws = (kt & 1) ? Ws1 : Ws0;

#pragma unroll
        for (int kk = 0; kk < BK; kk += 8) {
            uint32_t af[4][4];
#pragma unroll
            for (int mi = 0; mi < 4; mi++) {
                int r  = warpM * 64 + mi * 16 + (lane >> 2);
                int cc = kk + (lane & 3);
                af[mi][0] = f2u(As[r * A_STRIDE + cc]);
                af[mi][1] = f2u(As[(r + 8) * A_STRIDE + cc]);
                af[mi][2] = f2u(As[r * A_STRIDE + cc + 4]);
                af[mi][3] = f2u(As[(r + 8) * A_STRIDE + cc + 4]);
            }
            uint32_t bf[4][2];
#pragma unroll
            for (int ni = 0; ni < 4; ni++) {
                int n = warpN * 32 + ni * 8 + (lane >> 2);
                int k = kk + (lane & 3);
                bf[ni][0] = f2u(Ws[n * A_STRIDE + k]);
                bf[ni][1] = f2u(Ws[n * A_STRIDE + k + 4]);
            }
#pragma unroll
            for (int mi = 0; mi < 4; mi++)
#pragma unroll
                for (int ni = 0; ni < 4; ni++) mma_tf32(c[mi][ni], af[mi], bf[ni]);
        }
        __syncthreads();
    }

    // Epilogue: add bias, write h
#pragma unroll
    for (int ni = 0; ni < 4; ni++) {
        int cn = warpN * 32 + ni * 8 + ((lane & 3) << 1);
        float2 bb = *(const float2*)(bias + cn);
#pragma unroll
        for (int mi = 0; mi < 4; mi++) {
            int r = bm * BM + warpM * 64 + mi * 16 + (lane >> 2);
            float2 v0 = make_float2(c[mi][ni][0] + bb.x, c[mi][ni][1] + bb.y);
            float2 v1 = make_float2(c[mi][ni][2] + bb.x, c[mi][ni][3] + bb.y);
            *(float2*)&g_h[(size_t)r * OUTDIM + cn]       = v0;
            *(float2*)&g_h[(size_t)(r + 8) * OUTDIM + cn] = v1;
        }
    }
}

// ============================================================================
// Stage 2: out = A_hat @ h.  A_hat [NROWS, NROWS] row-major streamed via a
// 5-stage cp.async pipeline; h (8 MB) is L2-resident.
// ============================================================================
__global__ __launch_bounds__(256, 1)
void gemm_aggr(const float* __restrict__ A, float* __restrict__ out) {
    extern __shared__ float smem[];
    float* AsBase = smem;                                   // S * 4608 floats
    float* BsBase = smem + S_STAGES * A_STAGE_FLOATS;       // S * 4352 floats

    const int tid  = threadIdx.x;
    const int lane = tid & 31, wid = tid >> 5;
    const int warpM = wid >> 2, warpN = wid & 3;
    const int bm = blockIdx.x;

    const uint32_t sA = (uint32_t)__cvta_generic_to_shared(AsBase);
    const uint32_t sB = (uint32_t)__cvta_generic_to_shared(BsBase);

    float c[4][4][4];
#pragma unroll
    for (int i = 0; i < 4; i++)
#pragma unroll
        for (int j = 0; j < 4; j++)
#pragma unroll
            for (int k = 0; k < 4; k++) c[i][j][k] = 0.0f;

    // Prologue: issue tiles 0 .. S-2, one commit group each.
#pragma unroll
    for (int t = 0; t < S_STAGES - 1; t++) {
        load_tile_rowmajor(sA + (uint32_t)t * A_STAGE_FLOATS * 4u, A, bm * BM, t * BK, NROWS, tid);
        load_tile_kn(sB + (uint32_t)t * B_STAGE_FLOATS * 4u, g_h, t * BK, tid);
        cp_commit();
    }

    const int KT = NROWS / BK; // 512
    int st  = 0;               // compute stage = kt % S
    int wst = S_STAGES - 1;    // write stage  = (kt + S-1) % S

    for (int kt = 0; kt < KT; kt++) {
        // Oldest outstanding tile (kt) becomes visible once <= S-2 groups pending.
        asm volatile("cp.async.wait_group %0;" :: "n"(S_STAGES - 2) : "memory");
        __syncthreads();

        const float* As = AsBase + st * A_STAGE_FLOATS;
        const float* Bs = BsBase + st * B_STAGE_FLOATS;

#pragma unroll
        for (int kk = 0; kk < BK; kk += 8) {
            uint32_t af[4][4];
#pragma unroll
            for (int mi = 0; mi < 4; mi++) {
                int r  = warpM * 64 + mi * 16 + (lane >> 2);
                int cc = kk + (lane & 3);
                af[mi][0] = f2u(As[r * A_STRIDE + cc]);
                af[mi][1] = f2u(As[(r + 8) * A_STRIDE + cc]);
                af[mi][2] = f2u(As[r * A_STRIDE + cc + 4]);
                af[mi][3] = f2u(As[(r + 8) * A_STRIDE + cc + 4]);
            }
            uint32_t bf[4][2];
#pragma unroll
            for (int ni = 0; ni < 4; ni++) {
                int n = warpN * 32 + ni * 8 + (lane >> 2);
                int k = kk + (lane & 3);
                bf[ni][0] = f2u(Bs[k * B_STRIDE + n]);
                bf[ni][1] = f2u(Bs[(k + 4) * B_STRIDE + n]);
            }
#pragma unroll
            for (int mi = 0; mi < 4; mi++)
#pragma unroll
                for (int ni = 0; ni < 4; ni++) mma_tf32(c[mi][ni], af[mi], bf[ni]);
        }

        // Issue tile kt + S-1 into the stage freed at iteration kt-1.
        // All warps passed the __syncthreads above, so compute on that stage is done.
        int nt = kt + S_STAGES - 1;
        if (nt < KT) {
            load_tile_rowmajor(sA + (uint32_t)wst * A_STAGE_FLOATS * 4u, A, bm * BM, nt * BK, NROWS, tid);
            load_tile_kn(sB + (uint32_t)wst * B_STAGE_FLOATS * 4u, g_h, nt * BK, tid);
        }
        cp_commit();  // commit unconditionally to keep group accounting uniform

        if (++st  == S_STAGES) st  = 0;
        if (++wst == S_STAGES) wst = 0;
    }

    // Epilogue
#pragma unroll
    for (int mi = 0; mi < 4; mi++)
#pragma unroll
        for (int ni = 0; ni < 4; ni++) {
            int r  = bm * BM + warpM * 64 + mi * 16 + (lane >> 2);
            int cn = warpN * 32 + ni * 8 + ((lane & 3) << 1);
            *(float2*)&out[(size_t)r * OUTDIM + cn] =
                make_float2(c[mi][ni][0], c[mi][ni][1]);
            *(float2*)&out[(size_t)(r + 8) * OUTDIM + cn] =
                make_float2(c[mi][ni][2], c[mi][ni][3]);
        }
}

// Shared memory sizes (bytes)
static const int SMEM_LIN  = (2 * BM * A_STRIDE + 2 * BN * A_STRIDE) * 4;                // 73728
static const int SMEM_AGGR = (S_STAGES * A_STAGE_FLOATS + S_STAGES * B_STAGE_FLOATS) * 4; // 179200

extern "C" void kernel_launch(void* const* d_in, const int* in_sizes, int n_in,
                              void* d_out, int out_size) {
    const float* x     = (const float*)d_in[0];
    const float* A_hat = (const float*)d_in[1];
    const float* W     = (const float*)d_in[2];
    const float* b     = (const float*)d_in[3];
    float* out = (float*)d_out;

    cudaFuncSetAttribute(gemm_lin,  cudaFuncAttributeMaxDynamicSharedMemorySize, SMEM_LIN);
    cudaFuncSetAttribute(gemm_aggr, cudaFuncAttributeMaxDynamicSharedMemorySize, SMEM_AGGR);

    gemm_lin<<<NROWS / BM, 256, SMEM_LIN>>>(x, W, b);
    gemm_aggr<<<NROWS / BM, 256, SMEM_AGGR>>>(A_hat, out);
}